// round 5
// baseline (speedup 1.0000x reference)
#include <cuda_runtime.h>

// BalancedCELoss: loss = -sum(t==1 ? 1.6*log(p) : 0.4*log(1-p)) / N
//                 acc  = mean(round(p) == t)
// N = 16777216; HBM-bound (128 MiB streamed once).
// Single fused kernel, explicit MLP-8 load batching + streaming loads.

#define NBLK 2048
#define NTHR 256
#define STRIDE (NBLK * NTHR)

// log-domain weights: w * ln(2), accumulate log2 then the ln2 is pre-folded.
#define W1LN2 1.10903548889591f   /* 1.6 * ln(2) */
#define W0LN2 0.27725887222397f   /* 0.4 * ln(2) */

__device__ float        g_part_loss[NBLK];
__device__ float        g_part_acc[NBLK];
__device__ unsigned int g_done = 0;

__device__ __forceinline__ void bce_elem(float p, int t, float& lsum, float& asum)
{
    bool  pos = (t == 1);
    float arg = pos ? p : (1.0f - p);
    float w   = pos ? W1LN2 : W0LN2;
    lsum = fmaf(w, __log2f(arg), lsum);
    // round-half-to-even: 0.5 -> 0, so pred = (p > 0.5)
    asum += ((p > 0.5f) == pos) ? 1.0f : 0.0f;
}

__global__ void __launch_bounds__(NTHR, 4)
bce_fused_kernel(const float* __restrict__ inp, const int* __restrict__ tgt,
                 float* __restrict__ out, int n4, float inv_n)
{
    const float4* __restrict__ in4 = (const float4*)inp;
    const int4*   __restrict__ tg4 = (const int4*)tgt;

    int idx = blockIdx.x * NTHR + threadIdx.x;

    float lsum0 = 0.0f, lsum1 = 0.0f;
    float asum0 = 0.0f, asum1 = 0.0f;

    if (n4 == (STRIDE * 8)) {
        // Fast path: exactly 8 grid-stride iterations, 2 batches of 4.
        #pragma unroll
        for (int b = 0; b < 2; b++) {
            int i0 = idx + (b * 4 + 0) * STRIDE;
            int i1 = idx + (b * 4 + 1) * STRIDE;
            int i2 = idx + (b * 4 + 2) * STRIDE;
            int i3 = idx + (b * 4 + 3) * STRIDE;

            // Front-batched streaming loads: MLP = 8 per thread.
            float4 p0 = __ldcs(&in4[i0]);
            float4 p1 = __ldcs(&in4[i1]);
            float4 p2 = __ldcs(&in4[i2]);
            float4 p3 = __ldcs(&in4[i3]);
            int4   t0 = __ldcs(&tg4[i0]);
            int4   t1 = __ldcs(&tg4[i1]);
            int4   t2 = __ldcs(&tg4[i2]);
            int4   t3 = __ldcs(&tg4[i3]);

            bce_elem(p0.x, t0.x, lsum0, asum0);
            bce_elem(p0.y, t0.y, lsum1, asum1);
            bce_elem(p0.z, t0.z, lsum0, asum0);
            bce_elem(p0.w, t0.w, lsum1, asum1);
            bce_elem(p1.x, t1.x, lsum0, asum0);
            bce_elem(p1.y, t1.y, lsum1, asum1);
            bce_elem(p1.z, t1.z, lsum0, asum0);
            bce_elem(p1.w, t1.w, lsum1, asum1);
            bce_elem(p2.x, t2.x, lsum0, asum0);
            bce_elem(p2.y, t2.y, lsum1, asum1);
            bce_elem(p2.z, t2.z, lsum0, asum0);
            bce_elem(p2.w, t2.w, lsum1, asum1);
            bce_elem(p3.x, t3.x, lsum0, asum0);
            bce_elem(p3.y, t3.y, lsum1, asum1);
            bce_elem(p3.z, t3.z, lsum0, asum0);
            bce_elem(p3.w, t3.w, lsum1, asum1);
        }
    } else {
        // Generic fallback (any size divisible by 4).
        for (int i = idx; i < n4; i += STRIDE) {
            float4 p = __ldcs(&in4[i]);
            int4   t = __ldcs(&tg4[i]);
            bce_elem(p.x, t.x, lsum0, asum0);
            bce_elem(p.y, t.y, lsum1, asum1);
            bce_elem(p.z, t.z, lsum0, asum0);
            bce_elem(p.w, t.w, lsum1, asum1);
        }
    }

    float lsum = lsum0 + lsum1;
    float asum = asum0 + asum1;

    // warp reduce
    #pragma unroll
    for (int o = 16; o > 0; o >>= 1) {
        lsum += __shfl_down_sync(0xFFFFFFFFu, lsum, o);
        asum += __shfl_down_sync(0xFFFFFFFFu, asum, o);
    }

    __shared__ float sl[NTHR / 32];
    __shared__ float sa[NTHR / 32];
    __shared__ bool  s_last;
    int warp = threadIdx.x >> 5;
    int lane = threadIdx.x & 31;
    if (lane == 0) { sl[warp] = lsum; sa[warp] = asum; }
    __syncthreads();

    if (threadIdx.x == 0) {
        float l = 0.0f, a = 0.0f;
        #pragma unroll
        for (int w = 0; w < NTHR / 32; w++) { l += sl[w]; a += sa[w]; }
        g_part_loss[blockIdx.x] = l;
        g_part_acc[blockIdx.x]  = a;
        __threadfence();
        unsigned int prev = atomicAdd(&g_done, 1u);
        s_last = (prev == NBLK - 1);
    }
    __syncthreads();

    if (s_last) {
        // Last block reduces the 2048 partials in fixed order -> deterministic.
        float l = 0.0f, a = 0.0f;
        #pragma unroll
        for (int b = threadIdx.x; b < NBLK; b += NTHR) {
            l += g_part_loss[b];
            a += g_part_acc[b];
        }
        #pragma unroll
        for (int o = 16; o > 0; o >>= 1) {
            l += __shfl_down_sync(0xFFFFFFFFu, l, o);
            a += __shfl_down_sync(0xFFFFFFFFu, a, o);
        }
        if (lane == 0) { sl[warp] = l; sa[warp] = a; }
        __syncthreads();
        if (threadIdx.x == 0) {
            float lt = 0.0f, at = 0.0f;
            #pragma unroll
            for (int w = 0; w < NTHR / 32; w++) { lt += sl[w]; at += sa[w]; }
            out[0] = -lt * inv_n;
            out[1] =  at * inv_n;
            g_done = 0;   // reset for next graph replay
        }
    }
}

extern "C" void kernel_launch(void* const* d_in, const int* in_sizes, int n_in,
                              void* d_out, int out_size)
{
    const float* inp = (const float*)d_in[0];
    const int*   tgt = (const int*)d_in[1];
    float*       out = (float*)d_out;

    int n  = in_sizes[0];      // 16777216
    int n4 = n >> 2;           // float4 count (N divisible by 4)

    bce_fused_kernel<<<NBLK, NTHR>>>(inp, tgt, out, n4, 1.0f / (float)n);
}